// round 1
// baseline (speedup 1.0000x reference)
#include <cuda_runtime.h>
#include <cuda_bf16.h>

#define N_NODES 100000
#define N_EDGES 1600000
#define D 128          // IN_DIM == HID2
#define K_TOT 256      // concatenated K
#define TILE_M 64

// Scratch (allocation-free rule: __device__ globals)
__device__ float g_y[N_NODES * D];     // dinv[r] * x[r]
__device__ float g_agg[N_NODES * D];   // aggregated neighbor sum (init 2*y for double self-loops)
__device__ float g_dinv[N_NODES];
__device__ int   g_deg[N_NODES];

__global__ void k_init_deg() {
    int i = blockIdx.x * blockDim.x + threadIdx.x;
    if (i < N_NODES) g_deg[i] = 2;   // self-loops added twice in reference
}

__global__ void k_count(const int* __restrict__ col) {
    int e = blockIdx.x * blockDim.x + threadIdx.x;
    if (e < N_EDGES) atomicAdd(&g_deg[col[e]], 1);
}

__global__ void k_dinv() {
    int i = blockIdx.x * blockDim.x + threadIdx.x;
    if (i < N_NODES) g_dinv[i] = rsqrtf((float)g_deg[i]);
}

// y = dinv*x ; agg = 2*y (analytic double self-loop term)
__global__ void k_prepy(const float* __restrict__ x) {
    int idx = blockIdx.x * blockDim.x + threadIdx.x;   // float4 index
    if (idx >= N_NODES * (D / 4)) return;
    int node = idx >> 5;  // D/4 = 32 float4 per node
    float d = g_dinv[node];
    float4 v = ((const float4*)x)[idx];
    float4 y;
    y.x = d * v.x; y.y = d * v.y; y.z = d * v.z; y.w = d * v.w;
    ((float4*)g_y)[idx] = y;
    float4 a;
    a.x = 2.f * y.x; a.y = 2.f * y.y; a.z = 2.f * y.z; a.w = 2.f * y.w;
    ((float4*)g_agg)[idx] = a;
}

// One warp per edge: gather y[row] (float4/lane), atomicAdd into agg[col]
__global__ void k_scatter(const int* __restrict__ rowv, const int* __restrict__ colv) {
    int gw = (blockIdx.x * blockDim.x + threadIdx.x) >> 5;
    int lane = threadIdx.x & 31;
    if (gw >= N_EDGES) return;
    int r = rowv[gw];
    int c = colv[gw];
    float4 v = *(const float4*)(g_y + r * D + lane * 4);
    float* dst = g_agg + c * D + lane * 4;
    atomicAdd(dst + 0, v.x);
    atomicAdd(dst + 1, v.y);
    atomicAdd(dst + 2, v.z);
    atomicAdd(dst + 3, v.w);
}

// Fused GEMM: u = [dinv*agg, x] (K=256), V = u @ [W_conv; W_proj] + (b_conv+b_proj),
// out = relu(V) . W_out + b_out.  TILE_M=64 nodes/CTA, full N=128, full K=256 in smem.
__global__ __launch_bounds__(256, 1)
void k_gemm(const float* __restrict__ x,
            const float* __restrict__ Wconv, const float* __restrict__ bconv,
            const float* __restrict__ Wproj, const float* __restrict__ bproj,
            const float* __restrict__ Wout,  const float* __restrict__ bout,
            float* __restrict__ out) {
    extern __shared__ float sm[];
    float* sW = sm;                    // [256][128] K-major
    float* sU = sm + K_TOT * D;        // [64][256] node-major
    float* sB = sU + TILE_M * K_TOT;   // [128] fused bias
    float* sO = sB + D;                // [128] W_out

    int tid = threadIdx.x;
    int mBase = blockIdx.x * TILE_M;

    // Load weights: 8192 float4, 32 per thread
    const float4* Wc4 = (const float4*)Wconv;
    const float4* Wp4 = (const float4*)Wproj;
    float4* sW4 = (float4*)sW;
#pragma unroll
    for (int p = 0; p < 32; p++) {
        int idx = p * 256 + tid;       // float4 idx over [256][32]
        int k = idx >> 5;
        int n4 = idx & 31;
        sW4[idx] = (k < D) ? Wc4[k * 32 + n4] : Wp4[(k - D) * 32 + n4];
    }
    if (tid < D) {
        sB[tid] = bconv[tid] + bproj[tid];
        sO[tid] = Wout[tid];
    }

    // Load input tile: 4096 float4, 16 per thread. sU[m][k] node-major (matches gmem).
    float4* sU4 = (float4*)sU;
#pragma unroll
    for (int p = 0; p < 16; p++) {
        int idx = p * 256 + tid;       // float4 idx over [64][64]
        int m = idx >> 6;
        int kq = idx & 63;
        int node = mBase + m;
        float4 v = make_float4(0.f, 0.f, 0.f, 0.f);
        if (node < N_NODES) {
            if (kq < 32) {
                float d = g_dinv[node];
                float4 a = ((const float4*)g_agg)[node * 32 + kq];
                v.x = d * a.x; v.y = d * a.y; v.z = d * a.z; v.w = d * a.w;
            } else {
                v = ((const float4*)x)[node * 32 + (kq - 32)];
            }
        }
        sU4[idx] = v;
    }
    __syncthreads();

    int tx = tid & 15;   // 16 -> covers 128 cols, 8 each (split 2x float4)
    int ty = tid >> 4;   // 16 -> covers 64 rows, 4 each

    float acc[4][8];
#pragma unroll
    for (int r = 0; r < 4; r++)
#pragma unroll
        for (int j = 0; j < 8; j++) acc[r][j] = 0.f;

    for (int k = 0; k < K_TOT; k += 4) {
        float4 a[4];
#pragma unroll
        for (int r = 0; r < 4; r++)
            a[r] = *(const float4*)&sU[(ty * 4 + r) * K_TOT + k];
#pragma unroll
        for (int j = 0; j < 4; j++) {
            float4 b0 = sW4[(k + j) * 32 + tx];
            float4 b1 = sW4[(k + j) * 32 + 16 + tx];
#pragma unroll
            for (int r = 0; r < 4; r++) {
                float av = (j == 0) ? a[r].x : (j == 1) ? a[r].y : (j == 2) ? a[r].z : a[r].w;
                acc[r][0] += av * b0.x;
                acc[r][1] += av * b0.y;
                acc[r][2] += av * b0.z;
                acc[r][3] += av * b0.w;
                acc[r][4] += av * b1.x;
                acc[r][5] += av * b1.y;
                acc[r][6] += av * b1.z;
                acc[r][7] += av * b1.w;
            }
        }
    }

    // Epilogue: relu + dot with W_out, reduce across 16 tx lanes
    float bo = bout[0];
#pragma unroll
    for (int r = 0; r < 4; r++) {
        int node = mBase + ty * 4 + r;
        float s = 0.f;
#pragma unroll
        for (int j = 0; j < 4; j++) {
            int n = tx * 4 + j;
            float v = acc[r][j] + sB[n];
            s += fmaxf(v, 0.f) * sO[n];
        }
#pragma unroll
        for (int j = 0; j < 4; j++) {
            int n = 64 + tx * 4 + j;
            float v = acc[r][4 + j] + sB[n];
            s += fmaxf(v, 0.f) * sO[n];
        }
        s += __shfl_xor_sync(0xffffffff, s, 8);
        s += __shfl_xor_sync(0xffffffff, s, 4);
        s += __shfl_xor_sync(0xffffffff, s, 2);
        s += __shfl_xor_sync(0xffffffff, s, 1);
        if (tx == 0 && node < N_NODES) out[node] = s + bo;
    }
}

extern "C" void kernel_launch(void* const* d_in, const int* in_sizes, int n_in,
                              void* d_out, int out_size) {
    const float* x      = (const float*)d_in[0];
    const int*   ei     = (const int*)d_in[1];     // [2, E]: row then col
    const float* Wconv  = (const float*)d_in[2];
    const float* bconv  = (const float*)d_in[3];
    const float* Wproj  = (const float*)d_in[4];
    const float* bproj  = (const float*)d_in[5];
    const float* Wout   = (const float*)d_in[6];
    const float* bout   = (const float*)d_in[7];
    float* out = (float*)d_out;

    const int* rowv = ei;
    const int* colv = ei + N_EDGES;

    k_init_deg<<<(N_NODES + 255) / 256, 256>>>();
    k_count<<<(N_EDGES + 255) / 256, 256>>>(colv);
    k_dinv<<<(N_NODES + 255) / 256, 256>>>();
    k_prepy<<<(N_NODES * (D / 4) + 255) / 256, 256>>>(x);

    long long scatter_threads = (long long)N_EDGES * 32;
    k_scatter<<<(unsigned)((scatter_threads + 255) / 256), 256>>>(rowv, colv);

    int smem = (K_TOT * D + TILE_M * K_TOT + D + D) * sizeof(float);  // 197632 B
    static bool attr_set = false;
    if (!attr_set) {
        cudaFuncSetAttribute(k_gemm, cudaFuncAttributeMaxDynamicSharedMemorySize, smem);
        attr_set = true;
    }
    int grid = (N_NODES + TILE_M - 1) / TILE_M;
    k_gemm<<<grid, 256, smem>>>(x, Wconv, bconv, Wproj, bproj, Wout, bout, out);
}

// round 2
// speedup vs baseline: 2.0472x; 2.0472x over previous
#include <cuda_runtime.h>
#include <cuda_bf16.h>

#define N_NODES 100000
#define N_EDGES 1600000
#define D 128          // IN_DIM == HID2
#define K_TOT 256      // concatenated K
#define TILE_M 64
#define SCAN_BS 512
#define NB ((N_NODES + SCAN_BS - 1) / SCAN_BS)   // 196

// Scratch (allocation-free rule: __device__ globals)
__device__ float g_agg[N_NODES * D];   // sum_{r in N(c)} dinv[r]*x[r] + 2*dinv[c]*x[c]
__device__ float g_dinv[N_NODES];
__device__ int   g_cnt[N_NODES];       // in-degree (edges only)
__device__ int   g_cur[N_NODES];       // fill cursors
__device__ int   g_rowptr[N_NODES];    // CSR offsets (by destination)
__device__ int   g_src[N_EDGES];       // CSR adjacency: source nodes
__device__ int   g_bsum[NB];
__device__ int   g_bpre[NB];

__global__ void k_zero() {
    int i = blockIdx.x * blockDim.x + threadIdx.x;
    if (i < N_NODES) { g_cnt[i] = 0; g_cur[i] = 0; }
}

__global__ void k_count(const int* __restrict__ col) {
    int e = blockIdx.x * blockDim.x + threadIdx.x;
    if (e < N_EDGES) atomicAdd(&g_cnt[col[e]], 1);
}

// --- 3-kernel exclusive scan of g_cnt -> g_rowptr ---
__global__ void k_blocksum() {
    __shared__ int s[SCAN_BS];
    int t = threadIdx.x;
    int i = blockIdx.x * SCAN_BS + t;
    s[t] = (i < N_NODES) ? g_cnt[i] : 0;
    __syncthreads();
    for (int off = SCAN_BS / 2; off > 0; off >>= 1) {
        if (t < off) s[t] += s[t + off];
        __syncthreads();
    }
    if (t == 0) g_bsum[blockIdx.x] = s[0];
}

__global__ void k_scanbsum() {   // 1 block, 256 threads, NB=196 <= 256
    __shared__ int s[256];
    int t = threadIdx.x;
    int v = (t < NB) ? g_bsum[t] : 0;
    s[t] = v;
    __syncthreads();
    for (int off = 1; off < 256; off <<= 1) {
        int u = (t >= off) ? s[t - off] : 0;
        __syncthreads();
        s[t] += u;
        __syncthreads();
    }
    if (t < NB) g_bpre[t] = s[t] - v;   // exclusive
}

__global__ void k_scanblock() {
    __shared__ int s[SCAN_BS];
    int t = threadIdx.x;
    int i = blockIdx.x * SCAN_BS + t;
    int v = (i < N_NODES) ? g_cnt[i] : 0;
    s[t] = v;
    __syncthreads();
    for (int off = 1; off < SCAN_BS; off <<= 1) {
        int u = (t >= off) ? s[t - off] : 0;
        __syncthreads();
        s[t] += u;
        __syncthreads();
    }
    if (i < N_NODES) {
        g_rowptr[i] = s[t] - v + g_bpre[blockIdx.x];
        g_dinv[i] = rsqrtf((float)(v + 2));   // +2 double self-loop
    }
}

__global__ void k_fill(const int* __restrict__ rowv, const int* __restrict__ colv) {
    int e = blockIdx.x * blockDim.x + threadIdx.x;
    if (e >= N_EDGES) return;
    int c = colv[e];
    int pos = g_rowptr[c] + atomicAdd(&g_cur[c], 1);
    g_src[pos] = rowv[e];
}

// Warp-per-node gather aggregation
__global__ void k_agg(const float* __restrict__ x) {
    int w = (blockIdx.x * blockDim.x + threadIdx.x) >> 5;
    int lane = threadIdx.x & 31;
    if (w >= N_NODES) return;
    const float4* x4 = (const float4*)x;

    int start = g_rowptr[w];
    int cn = g_cnt[w];
    float dc = g_dinv[w];
    float4 xv = x4[w * 32 + lane];
    float ax = 2.f * dc * xv.x, ay = 2.f * dc * xv.y, az = 2.f * dc * xv.z, aw = 2.f * dc * xv.w;

    for (int base = 0; base < cn; base += 32) {
        int idx = 0;
        if (base + lane < cn) idx = g_src[start + base + lane];
        int m = min(32, cn - base);
        int j = 0;
        for (; j + 4 <= m; j += 4) {
            int s0 = __shfl_sync(0xffffffffu, idx, j);
            int s1 = __shfl_sync(0xffffffffu, idx, j + 1);
            int s2 = __shfl_sync(0xffffffffu, idx, j + 2);
            int s3 = __shfl_sync(0xffffffffu, idx, j + 3);
            float d0 = g_dinv[s0], d1 = g_dinv[s1], d2 = g_dinv[s2], d3 = g_dinv[s3];
            float4 v0 = x4[s0 * 32 + lane];
            float4 v1 = x4[s1 * 32 + lane];
            float4 v2 = x4[s2 * 32 + lane];
            float4 v3 = x4[s3 * 32 + lane];
            ax += d0 * v0.x + d1 * v1.x + d2 * v2.x + d3 * v3.x;
            ay += d0 * v0.y + d1 * v1.y + d2 * v2.y + d3 * v3.y;
            az += d0 * v0.z + d1 * v1.z + d2 * v2.z + d3 * v3.z;
            aw += d0 * v0.w + d1 * v1.w + d2 * v2.w + d3 * v3.w;
        }
        for (; j < m; j++) {
            int s0 = __shfl_sync(0xffffffffu, idx, j);
            float d0 = g_dinv[s0];
            float4 v0 = x4[s0 * 32 + lane];
            ax += d0 * v0.x; ay += d0 * v0.y; az += d0 * v0.z; aw += d0 * v0.w;
        }
    }
    ((float4*)g_agg)[w * 32 + lane] = make_float4(ax, ay, az, aw);
}

__device__ __forceinline__ unsigned long long ffma2(unsigned long long a, unsigned long long b,
                                                    unsigned long long c) {
    unsigned long long d;
    asm("fma.rn.f32x2 %0, %1, %2, %3;" : "=l"(d) : "l"(a), "l"(b), "l"(c));
    return d;
}
__device__ __forceinline__ unsigned long long packf2(float v) {
    unsigned long long d;
    asm("mov.b64 %0, {%1, %1};" : "=l"(d) : "f"(v));
    return d;
}
__device__ __forceinline__ void unpackf2(unsigned long long p, float& lo, float& hi) {
    asm("mov.b64 {%0, %1}, %2;" : "=f"(lo), "=f"(hi) : "l"(p));
}

// Fused GEMM: u = [dinv*agg, x] (K=256), V = u @ [W_conv; W_proj] + (b_conv+b_proj),
// out = relu(V) . W_out + b_out.  Packed f32x2 FMAs in the inner loop.
__global__ __launch_bounds__(256, 1)
void k_gemm(const float* __restrict__ x,
            const float* __restrict__ Wconv, const float* __restrict__ bconv,
            const float* __restrict__ Wproj, const float* __restrict__ bproj,
            const float* __restrict__ Wout,  const float* __restrict__ bout,
            float* __restrict__ out) {
    extern __shared__ float sm[];
    float* sW = sm;                    // [256][128] K-major
    float* sU = sm + K_TOT * D;        // [64][256] node-major
    float* sB = sU + TILE_M * K_TOT;   // [128] fused bias
    float* sO = sB + D;                // [128] W_out

    int tid = threadIdx.x;
    int mBase = blockIdx.x * TILE_M;

    const float4* Wc4 = (const float4*)Wconv;
    const float4* Wp4 = (const float4*)Wproj;
    float4* sW4 = (float4*)sW;
#pragma unroll
    for (int p = 0; p < 32; p++) {
        int idx = p * 256 + tid;       // float4 idx over [256][32]
        int k = idx >> 5;
        int n4 = idx & 31;
        sW4[idx] = (k < D) ? Wc4[k * 32 + n4] : Wp4[(k - D) * 32 + n4];
    }
    if (tid < D) {
        sB[tid] = bconv[tid] + bproj[tid];
        sO[tid] = Wout[tid];
    }

    float4* sU4 = (float4*)sU;
#pragma unroll
    for (int p = 0; p < 16; p++) {
        int idx = p * 256 + tid;       // float4 idx over [64][64]
        int m = idx >> 6;
        int kq = idx & 63;
        int node = mBase + m;
        float4 v = make_float4(0.f, 0.f, 0.f, 0.f);
        if (node < N_NODES) {
            if (kq < 32) {
                float d = g_dinv[node];
                float4 a = ((const float4*)g_agg)[node * 32 + kq];
                v.x = d * a.x; v.y = d * a.y; v.z = d * a.z; v.w = d * a.w;
            } else {
                v = ((const float4*)x)[node * 32 + (kq - 32)];
            }
        }
        sU4[idx] = v;
    }
    __syncthreads();

    int tx = tid & 15;   // 16 -> 128 cols, 8 each
    int ty = tid >> 4;   // 16 -> 64 rows, 4 each

    unsigned long long acc2[4][4];
#pragma unroll
    for (int r = 0; r < 4; r++)
#pragma unroll
        for (int p = 0; p < 4; p++) acc2[r][p] = 0ull;

    const ulonglong2* sW2 = (const ulonglong2*)sW;

    for (int k = 0; k < K_TOT; k += 4) {
        float4 a[4];
#pragma unroll
        for (int r = 0; r < 4; r++)
            a[r] = *(const float4*)&sU[(ty * 4 + r) * K_TOT + k];
#pragma unroll
        for (int j = 0; j < 4; j++) {
            ulonglong2 b0 = sW2[(k + j) * 32 + tx];        // cols 4tx..4tx+3
            ulonglong2 b1 = sW2[(k + j) * 32 + 16 + tx];   // cols 64+4tx..64+4tx+3
#pragma unroll
            for (int r = 0; r < 4; r++) {
                float av = (j == 0) ? a[r].x : (j == 1) ? a[r].y : (j == 2) ? a[r].z : a[r].w;
                unsigned long long av2 = packf2(av);
                acc2[r][0] = ffma2(av2, b0.x, acc2[r][0]);
                acc2[r][1] = ffma2(av2, b0.y, acc2[r][1]);
                acc2[r][2] = ffma2(av2, b1.x, acc2[r][2]);
                acc2[r][3] = ffma2(av2, b1.y, acc2[r][3]);
            }
        }
    }

    // Epilogue: relu + dot with W_out, reduce across 16 tx lanes
    float bo = bout[0];
#pragma unroll
    for (int r = 0; r < 4; r++) {
        int node = mBase + ty * 4 + r;
        float s = 0.f;
#pragma unroll
        for (int p = 0; p < 4; p++) {
            float lo, hi;
            unpackf2(acc2[r][p], lo, hi);
            int nb = (p < 2) ? (tx * 4 + p * 2) : (64 + tx * 4 + (p - 2) * 2);
            float v0 = lo + sB[nb];
            float v1 = hi + sB[nb + 1];
            s += fmaxf(v0, 0.f) * sO[nb];
            s += fmaxf(v1, 0.f) * sO[nb + 1];
        }
        s += __shfl_xor_sync(0xffffffff, s, 8);
        s += __shfl_xor_sync(0xffffffff, s, 4);
        s += __shfl_xor_sync(0xffffffff, s, 2);
        s += __shfl_xor_sync(0xffffffff, s, 1);
        if (tx == 0 && node < N_NODES) out[node] = s + bo;
    }
}

extern "C" void kernel_launch(void* const* d_in, const int* in_sizes, int n_in,
                              void* d_out, int out_size) {
    const float* x      = (const float*)d_in[0];
    const int*   ei     = (const int*)d_in[1];     // [2, E]: row then col
    const float* Wconv  = (const float*)d_in[2];
    const float* bconv  = (const float*)d_in[3];
    const float* Wproj  = (const float*)d_in[4];
    const float* bproj  = (const float*)d_in[5];
    const float* Wout   = (const float*)d_in[6];
    const float* bout   = (const float*)d_in[7];
    float* out = (float*)d_out;

    const int* rowv = ei;
    const int* colv = ei + N_EDGES;

    k_zero<<<(N_NODES + 255) / 256, 256>>>();
    k_count<<<(N_EDGES + 255) / 256, 256>>>(colv);
    k_blocksum<<<NB, SCAN_BS>>>();
    k_scanbsum<<<1, 256>>>();
    k_scanblock<<<NB, SCAN_BS>>>();
    k_fill<<<(N_EDGES + 255) / 256, 256>>>(rowv, colv);

    long long agg_threads = (long long)N_NODES * 32;
    k_agg<<<(unsigned)((agg_threads + 255) / 256), 256>>>(x);

    int smem = (K_TOT * D + TILE_M * K_TOT + D + D) * sizeof(float);  // 197632 B
    static bool attr_set = false;
    if (!attr_set) {
        cudaFuncSetAttribute(k_gemm, cudaFuncAttributeMaxDynamicSharedMemorySize, smem);
        attr_set = true;
    }
    int grid = (N_NODES + TILE_M - 1) / TILE_M;
    k_gemm<<<grid, 256, smem>>>(x, Wconv, bconv, Wproj, bproj, Wout, bout, out);
}

// round 4
// speedup vs baseline: 3.3714x; 1.6469x over previous
#include <cuda_runtime.h>
#include <cuda_bf16.h>
#include <cstdint>

#define N_NODES 100000
#define N_EDGES 1600000
#define D 128
#define SCAN_BS 512
#define NB ((N_NODES + SCAN_BS - 1) / SCAN_BS)   // 196
#define GEMM_TILE_M 128
#define GEMM_GRID ((N_NODES + GEMM_TILE_M - 1) / GEMM_TILE_M)   // 782
#define PITCH_B 272   // bytes per smem row: 128 bf16 = 256B + 16B pad (conflict-free ldmatrix)

// ---------------- scratch (__device__ globals; no allocation allowed) -------
__device__ float g_agg[N_NODES * D];
__device__ float g_dinv[N_NODES];
__device__ int   g_cnt[N_NODES];
__device__ int   g_cur[N_NODES];
__device__ int   g_rowptr[N_NODES];
__device__ int   g_src[N_EDGES];
__device__ int   g_bsum[NB];
__device__ int   g_bpre[NB];
// bf16 hi/lo weight images, layout [half][n:128][k:128] (B[n][k] = W[k_global][n])
__device__ __align__(16) unsigned char g_Bhi[65536];
__device__ __align__(16) unsigned char g_Blo[65536];

// ---------------- degree / CSR build ---------------------------------------
__global__ void k_zero() {
    int i = blockIdx.x * blockDim.x + threadIdx.x;
    if (i < N_NODES) { g_cnt[i] = 0; g_cur[i] = 0; }
}

__global__ void k_count(const int* __restrict__ col) {
    int e = blockIdx.x * blockDim.x + threadIdx.x;
    if (e < N_EDGES) atomicAdd(&g_cnt[col[e]], 1);
}

__global__ void k_blocksum() {
    __shared__ int s[SCAN_BS];
    int t = threadIdx.x;
    int i = blockIdx.x * SCAN_BS + t;
    s[t] = (i < N_NODES) ? g_cnt[i] : 0;
    __syncthreads();
    for (int off = SCAN_BS / 2; off > 0; off >>= 1) {
        if (t < off) s[t] += s[t + off];
        __syncthreads();
    }
    if (t == 0) g_bsum[blockIdx.x] = s[0];
}

__global__ void k_scanbsum() {
    __shared__ int s[256];
    int t = threadIdx.x;
    int v = (t < NB) ? g_bsum[t] : 0;
    s[t] = v;
    __syncthreads();
    for (int off = 1; off < 256; off <<= 1) {
        int u = (t >= off) ? s[t - off] : 0;
        __syncthreads();
        s[t] += u;
        __syncthreads();
    }
    if (t < NB) g_bpre[t] = s[t] - v;
}

__global__ void k_scanblock() {
    __shared__ int s[SCAN_BS];
    int t = threadIdx.x;
    int i = blockIdx.x * SCAN_BS + t;
    int v = (i < N_NODES) ? g_cnt[i] : 0;
    s[t] = v;
    __syncthreads();
    for (int off = 1; off < SCAN_BS; off <<= 1) {
        int u = (t >= off) ? s[t - off] : 0;
        __syncthreads();
        s[t] += u;
        __syncthreads();
    }
    if (i < N_NODES) {
        g_rowptr[i] = s[t] - v + g_bpre[blockIdx.x];
        g_dinv[i] = rsqrtf((float)(v + 2));
    }
}

__global__ void k_fill(const int* __restrict__ rowv, const int* __restrict__ colv) {
    int e = blockIdx.x * blockDim.x + threadIdx.x;
    if (e >= N_EDGES) return;
    int c = colv[e];
    int pos = g_rowptr[c] + atomicAdd(&g_cur[c], 1);
    g_src[pos] = rowv[e];
}

// ---------------- warp-per-node gather aggregation --------------------------
__global__ void k_agg(const float* __restrict__ x) {
    int w = (blockIdx.x * blockDim.x + threadIdx.x) >> 5;
    int lane = threadIdx.x & 31;
    if (w >= N_NODES) return;
    const float4* x4 = (const float4*)x;

    int start = g_rowptr[w];
    int cn = g_cnt[w];
    float dc = g_dinv[w];
    float4 xv = x4[w * 32 + lane];
    float ax = 2.f * dc * xv.x, ay = 2.f * dc * xv.y, az = 2.f * dc * xv.z, aw = 2.f * dc * xv.w;

    for (int base = 0; base < cn; base += 32) {
        int idx = 0;
        if (base + lane < cn) idx = g_src[start + base + lane];
        int m = min(32, cn - base);
        int j = 0;
        for (; j + 4 <= m; j += 4) {
            int s0 = __shfl_sync(0xffffffffu, idx, j);
            int s1 = __shfl_sync(0xffffffffu, idx, j + 1);
            int s2 = __shfl_sync(0xffffffffu, idx, j + 2);
            int s3 = __shfl_sync(0xffffffffu, idx, j + 3);
            float d0 = g_dinv[s0], d1 = g_dinv[s1], d2 = g_dinv[s2], d3 = g_dinv[s3];
            float4 v0 = x4[s0 * 32 + lane];
            float4 v1 = x4[s1 * 32 + lane];
            float4 v2 = x4[s2 * 32 + lane];
            float4 v3 = x4[s3 * 32 + lane];
            ax += d0 * v0.x + d1 * v1.x + d2 * v2.x + d3 * v3.x;
            ay += d0 * v0.y + d1 * v1.y + d2 * v2.y + d3 * v3.y;
            az += d0 * v0.z + d1 * v1.z + d2 * v2.z + d3 * v3.z;
            aw += d0 * v0.w + d1 * v1.w + d2 * v2.w + d3 * v3.w;
        }
        for (; j < m; j++) {
            int s0 = __shfl_sync(0xffffffffu, idx, j);
            float d0 = g_dinv[s0];
            float4 v0 = x4[s0 * 32 + lane];
            ax += d0 * v0.x; ay += d0 * v0.y; az += d0 * v0.z; aw += d0 * v0.w;
        }
    }
    ((float4*)g_agg)[w * 32 + lane] = make_float4(ax, ay, az, aw);
}

// ---------------- weight pre-conversion (plain [half][n][k] layout) ---------
__global__ void k_wconv(const float* __restrict__ Wconv, const float* __restrict__ Wproj) {
    int t = blockIdx.x * blockDim.x + threadIdx.x;  // 16384 = 128 n * 128 k-pairs
    if (t >= 128 * 128) return;
    int n = t >> 7;
    int p = t & 127;
    int k0 = 2 * p, k1 = k0 + 1;
    float v0 = (k0 < D) ? Wconv[k0 * D + n] : Wproj[(k0 - D) * D + n];
    float v1 = (k1 < D) ? Wconv[k1 * D + n] : Wproj[(k1 - D) * D + n];
    __nv_bfloat16 h0 = __float2bfloat16_rn(v0);
    __nv_bfloat16 h1 = __float2bfloat16_rn(v1);
    __nv_bfloat16 l0 = __float2bfloat16_rn(v0 - __bfloat162float(h0));
    __nv_bfloat16 l1 = __float2bfloat16_rn(v1 - __bfloat162float(h1));
    uint32_t hp = (uint32_t)__bfloat16_as_ushort(h0) | ((uint32_t)__bfloat16_as_ushort(h1) << 16);
    uint32_t lp = (uint32_t)__bfloat16_as_ushort(l0) | ((uint32_t)__bfloat16_as_ushort(l1) << 16);
    int half = k0 >> 7;
    int klocal = k0 & 127;
    uint32_t off = ((uint32_t)half * 16384 + n * 128 + klocal) * 2;   // bytes
    *(uint32_t*)(g_Bhi + off) = hp;
    *(uint32_t*)(g_Blo + off) = lp;
}

// ---------------- mma.sync split-bf16 GEMM + fused epilogue -----------------
// smem byte offsets
#define SM_AHI 0
#define SM_ALO 34816
#define SM_BHI 69632
#define SM_BLO 104448
#define SM_MISC 139264
#define SM_TOTAL 140800
// misc: sB[128]f @ +0, sO[128]f @ +512, sRes[128]f @ +1024

__device__ __forceinline__ uint32_t s2u(const void* p) {
    uint32_t a;
    asm("{ .reg .u64 t; cvta.to.shared.u64 t, %1; cvt.u32.u64 %0, t; }" : "=r"(a) : "l"(p));
    return a;
}
__device__ __forceinline__ void ldsm4(uint32_t* r, uint32_t addr) {
    asm volatile("ldmatrix.sync.aligned.m8n8.x4.shared.b16 {%0,%1,%2,%3}, [%4];"
                 : "=r"(r[0]), "=r"(r[1]), "=r"(r[2]), "=r"(r[3]) : "r"(addr));
}
__device__ __forceinline__ void mma16816(float* c, const uint32_t* a, uint32_t b0, uint32_t b1) {
    asm volatile(
        "mma.sync.aligned.m16n8k16.row.col.f32.bf16.bf16.f32 "
        "{%0,%1,%2,%3}, {%4,%5,%6,%7}, {%8,%9}, {%0,%1,%2,%3};"
        : "+f"(c[0]), "+f"(c[1]), "+f"(c[2]), "+f"(c[3])
        : "r"(a[0]), "r"(a[1]), "r"(a[2]), "r"(a[3]), "r"(b0), "r"(b1));
}

__global__ __launch_bounds__(256, 1)
void k_gemm(const float* __restrict__ x,
            const float* __restrict__ bconv, const float* __restrict__ bproj,
            const float* __restrict__ Wout,  const float* __restrict__ bout,
            float* __restrict__ out) {
    extern __shared__ char sm[];
    uint32_t sb = s2u(sm);
    int tid = threadIdx.x;
    int wid = tid >> 5;
    int lane = tid & 31;
    int mBase = blockIdx.x * GEMM_TILE_M;

    float* sB = (float*)(sm + SM_MISC);
    float* sO = (float*)(sm + SM_MISC + 512);
    float* sRes = (float*)(sm + SM_MISC + 1024);

    if (tid < D) {
        sB[tid] = bconv[tid] + bproj[tid];
        sO[tid] = Wout[tid];
        sRes[tid] = 0.f;
    }

    int warp_m = wid >> 1;   // 0..3 -> rows 32*warp_m
    int warp_n = wid & 1;    // 0..1 -> cols 64*warp_n

    float acc[2][8][4];
#pragma unroll
    for (int mt = 0; mt < 2; mt++)
#pragma unroll
        for (int nt = 0; nt < 8; nt++)
#pragma unroll
            for (int j = 0; j < 4; j++) acc[mt][nt][j] = 0.f;

    const float4* agg4 = (const float4*)g_agg;
    const float4* x4 = (const float4*)x;
    int l8 = lane & 7;
    int sel = lane >> 3;

    for (int h = 0; h < 2; h++) {
        __syncthreads();   // previous-half smem fully consumed (also covers sB/sO init)

        // ---- convert A half into smem hi/lo, padded rows ----
#pragma unroll
        for (int p = 0; p < 16; p++) {
            int i = p * 256 + tid;      // 4096 float4 over [128 rows][32 q]
            int m = i >> 5;
            int q = i & 31;             // k = 4q
            int node = mBase + m;
            float4 v = make_float4(0.f, 0.f, 0.f, 0.f);
            if (node < N_NODES) {
                if (h == 0) {
                    float dcs = g_dinv[node];
                    float4 a = agg4[node * 32 + q];
                    v.x = dcs * a.x; v.y = dcs * a.y; v.z = dcs * a.z; v.w = dcs * a.w;
                } else {
                    v = x4[node * 32 + q];
                }
            }
            __nv_bfloat16 h0 = __float2bfloat16_rn(v.x);
            __nv_bfloat16 h1 = __float2bfloat16_rn(v.y);
            __nv_bfloat16 h2 = __float2bfloat16_rn(v.z);
            __nv_bfloat16 h3 = __float2bfloat16_rn(v.w);
            __nv_bfloat16 l0 = __float2bfloat16_rn(v.x - __bfloat162float(h0));
            __nv_bfloat16 l1 = __float2bfloat16_rn(v.y - __bfloat162float(h1));
            __nv_bfloat16 l2 = __float2bfloat16_rn(v.z - __bfloat162float(h2));
            __nv_bfloat16 l3 = __float2bfloat16_rn(v.w - __bfloat162float(h3));
            uint32_t hp0 = (uint32_t)__bfloat16_as_ushort(h0) | ((uint32_t)__bfloat16_as_ushort(h1) << 16);
            uint32_t hp1 = (uint32_t)__bfloat16_as_ushort(h2) | ((uint32_t)__bfloat16_as_ushort(h3) << 16);
            uint32_t lp0 = (uint32_t)__bfloat16_as_ushort(l0) | ((uint32_t)__bfloat16_as_ushort(l1) << 16);
            uint32_t lp1 = (uint32_t)__bfloat16_as_ushort(l2) | ((uint32_t)__bfloat16_as_ushort(l3) << 16);
            uint32_t off = (uint32_t)m * PITCH_B + q * 8;
            *(uint32_t*)(sm + SM_AHI + off) = hp0;
            *(uint32_t*)(sm + SM_AHI + off + 4) = hp1;
            *(uint32_t*)(sm + SM_ALO + off) = lp0;
            *(uint32_t*)(sm + SM_ALO + off + 4) = lp1;
        }

        // ---- copy B half (hi+lo) into padded smem ----
#pragma unroll
        for (int p = 0; p < 16; p++) {
            int i = p * 256 + tid;      // 4096 over 2 images x 2048 uint4
            int img = i >> 11;
            int j = i & 2047;
            int r = j >> 4;
            int u = j & 15;
            const unsigned char* src = (img == 0 ? g_Bhi : g_Blo) + h * 32768 + r * 256 + u * 16;
            unsigned char* dst = (unsigned char*)sm + (img == 0 ? SM_BHI : SM_BLO) + r * PITCH_B + u * 16;
            *(uint4*)dst = *(const uint4*)src;
        }
        __syncthreads();

        // ---- MMA mainloop: 8 k-steps of 16 ----
        uint32_t aBaseHi = sb + SM_AHI + (warp_m * 32) * PITCH_B;
        uint32_t aBaseLo = sb + SM_ALO + (warp_m * 32) * PITCH_B;
        uint32_t bBaseHi = sb + SM_BHI + (warp_n * 64) * PITCH_B;
        uint32_t bBaseLo = sb + SM_BLO + (warp_n * 64) * PITCH_B;

#pragma unroll
        for (int ks = 0; ks < 8; ks++) {
            int kb = ks * 16;
            uint32_t ah[2][4], al[2][4];
#pragma unroll
            for (int mt = 0; mt < 2; mt++) {
                int row = mt * 16 + l8 + (sel & 1) * 8;
                int kk = kb + (sel >> 1) * 8;
                uint32_t o = (uint32_t)row * PITCH_B + kk * 2;
                ldsm4(ah[mt], aBaseHi + o);
                ldsm4(al[mt], aBaseLo + o);
            }
#pragma unroll
            for (int ntp = 0; ntp < 4; ntp++) {
                int row = ntp * 16 + (sel >> 1) * 8 + l8;
                int kk = kb + (sel & 1) * 8;
                uint32_t o = (uint32_t)row * PITCH_B + kk * 2;
                uint32_t bh[4], bl[4];
                ldsm4(bh, bBaseHi + o);
                ldsm4(bl, bBaseLo + o);
#pragma unroll
                for (int mt = 0; mt < 2; mt++) {
                    mma16816(acc[mt][ntp * 2],     ah[mt], bh[0], bh[1]);   // AhBh
                    mma16816(acc[mt][ntp * 2 + 1], ah[mt], bh[2], bh[3]);
                    mma16816(acc[mt][ntp * 2],     ah[mt], bl[0], bl[1]);   // AhBl
                    mma16816(acc[mt][ntp * 2 + 1], ah[mt], bl[2], bl[3]);
                    mma16816(acc[mt][ntp * 2],     al[mt], bh[0], bh[1]);   // AlBh
                    mma16816(acc[mt][ntp * 2 + 1], al[mt], bh[2], bh[3]);
                }
            }
        }
    }

    // ---- epilogue: relu + dot(W_out), smem atomic combine across warp cols ----
    __syncthreads();
#pragma unroll
    for (int mt = 0; mt < 2; mt++) {
        int r0 = warp_m * 32 + mt * 16 + (lane >> 2);
        float s0 = 0.f, s1 = 0.f;
#pragma unroll
        for (int nt = 0; nt < 8; nt++) {
            int c = warp_n * 64 + nt * 8 + 2 * (lane & 3);
            s0 += fmaxf(acc[mt][nt][0] + sB[c], 0.f) * sO[c];
            s0 += fmaxf(acc[mt][nt][1] + sB[c + 1], 0.f) * sO[c + 1];
            s1 += fmaxf(acc[mt][nt][2] + sB[c], 0.f) * sO[c];
            s1 += fmaxf(acc[mt][nt][3] + sB[c + 1], 0.f) * sO[c + 1];
        }
        atomicAdd(&sRes[r0], s0);
        atomicAdd(&sRes[r0 + 8], s1);
    }
    __syncthreads();
    if (tid < GEMM_TILE_M) {
        int node = mBase + tid;
        if (node < N_NODES) out[node] = sRes[tid] + bout[0];
    }
}

// ---------------- launch -----------------------------------------------------
extern "C" void kernel_launch(void* const* d_in, const int* in_sizes, int n_in,
                              void* d_out, int out_size) {
    const float* x      = (const float*)d_in[0];
    const int*   ei     = (const int*)d_in[1];
    const float* Wconv  = (const float*)d_in[2];
    const float* bconv  = (const float*)d_in[3];
    const float* Wproj  = (const float*)d_in[4];
    const float* bproj  = (const float*)d_in[5];
    const float* Wout   = (const float*)d_in[6];
    const float* bout   = (const float*)d_in[7];
    float* out = (float*)d_out;

    const int* rowv = ei;
    const int* colv = ei + N_EDGES;

    k_wconv<<<64, 256>>>(Wconv, Wproj);
    k_zero<<<(N_NODES + 255) / 256, 256>>>();
    k_count<<<(N_EDGES + 255) / 256, 256>>>(colv);
    k_blocksum<<<NB, SCAN_BS>>>();
    k_scanbsum<<<1, 256>>>();
    k_scanblock<<<NB, SCAN_BS>>>();
    k_fill<<<(N_EDGES + 255) / 256, 256>>>(rowv, colv);

    long long agg_threads = (long long)N_NODES * 32;
    k_agg<<<(unsigned)((agg_threads + 255) / 256), 256>>>(x);

    static bool attr_set = false;
    if (!attr_set) {
        cudaFuncSetAttribute(k_gemm, cudaFuncAttributeMaxDynamicSharedMemorySize, SM_TOTAL);
        attr_set = true;
    }
    k_gemm<<<GEMM_GRID, 256, SM_TOTAL>>>(x, bconv, bproj, Wout, bout, out);
}